// round 16
// baseline (speedup 1.0000x reference)
#include <cuda_runtime.h>
#include <cuda_fp16.h>
#include <cstdint>
#include <cstddef>

// Problem constants
static constexpr int NN = 65536;
static constexpr int MROWS = 2 * NN;     // 131072 token rows
static constexpr int NBLK = MROWS / 128; // 1024 blocks

// ---------------- device scratch ----------------
// Combined per-head weights: [k=256][h*128 + (0..63: W_fx_h | 64..127: (W_x_h@W_slice)*invt)]
__device__ __half g_Wcomb[256 * 1024];
__device__ float  g_biasL[8 * 64];        // (b_x_h @ W_slice + b_slice) * invt
__device__ __half g_Xh[(size_t)MROWS * 256];        // 64 MB fp16 copy of x
__device__ __half g_Part[(size_t)NBLK * 8 * 4096];  // 64 MB fp16 partials
__device__ float  g_PartN[NBLK * 8 * 64];

// ---------------- ptx helpers ----------------
__device__ __forceinline__ uint32_t smem_u32(const void* p) {
    return (uint32_t)__cvta_generic_to_shared(p);
}
__device__ __forceinline__ void ldm_x4(uint32_t* r, uint32_t addr) {
    asm volatile("ldmatrix.sync.aligned.m8n8.x4.shared.b16 {%0,%1,%2,%3}, [%4];"
                 : "=r"(r[0]), "=r"(r[1]), "=r"(r[2]), "=r"(r[3]) : "r"(addr));
}
__device__ __forceinline__ void ldm_x4_t(uint32_t* r, uint32_t addr) {
    asm volatile("ldmatrix.sync.aligned.m8n8.x4.trans.shared.b16 {%0,%1,%2,%3}, [%4];"
                 : "=r"(r[0]), "=r"(r[1]), "=r"(r[2]), "=r"(r[3]) : "r"(addr));
}
__device__ __forceinline__ void mma_f16(float* c, const uint32_t* a, uint32_t b0, uint32_t b1) {
    asm volatile("mma.sync.aligned.m16n8k16.row.col.f32.f16.f16.f32 "
                 "{%0,%1,%2,%3}, {%4,%5,%6,%7}, {%8,%9}, {%0,%1,%2,%3};"
                 : "+f"(c[0]), "+f"(c[1]), "+f"(c[2]), "+f"(c[3])
                 : "r"(a[0]), "r"(a[1]), "r"(a[2]), "r"(a[3]), "r"(b0), "r"(b1));
}
__device__ __forceinline__ void cp16(uint32_t smem_addr, const void* gptr) {
    asm volatile("cp.async.cg.shared.global [%0], [%1], 16;"
                 :: "r"(smem_addr), "l"(gptr) : "memory");
}
__device__ __forceinline__ void cp_commit() {
    asm volatile("cp.async.commit_group;" ::: "memory");
}
__device__ __forceinline__ void cp_wait0() {
    asm volatile("cp.async.wait_group 0;" ::: "memory");
}

// ---------------- prep kernels (split for launch-slot layout) ----------------
// prep_w: fold W_slice + 1/temp into logit weight columns; copy f columns.
// Two launches, each 512 blocks, covering half the k range via offset.
__global__ void __launch_bounds__(256) prep_w(
        const float* __restrict__ Wx,
        const float* __restrict__ Wfx,
        const float* __restrict__ Wsl,
        const float* __restrict__ temp,
        int offset) {
    __shared__ float sW[64 * 64];
    for (int i = threadIdx.x; i < 4096; i += 256) sW[i] = Wsl[i];
    __syncthreads();

    int idx = (offset * 512 + blockIdx.x) * 256 + threadIdx.x;   // 0..262143 over 2 launches
    int k = idx >> 10, j = idx & 1023;
    int h = j >> 7, c = j & 127;
    if (c < 64) {
        g_Wcomb[k * 1024 + h * 128 + c] = __float2half(Wfx[k * 512 + h * 64 + c]);
    } else {
        int s = c - 64;
        float t = fminf(fmaxf(temp[h], 0.5f), 5.0f);
        float invt = 1.0f / t;
        float acc = 0.f;
        #pragma unroll 8
        for (int d = 0; d < 64; d++)
            acc += Wx[k * 512 + h * 64 + d] * sW[d * 64 + s];
        g_Wcomb[k * 1024 + h * 128 + c] = __float2half(acc * invt);
    }
}

// prep_b: fold logit bias. 2 blocks x 256.
__global__ void __launch_bounds__(256) prep_b(
        const float* __restrict__ bx,
        const float* __restrict__ Wsl, const float* __restrict__ bsl,
        const float* __restrict__ temp) {
    __shared__ float sW[64 * 64];
    for (int i = threadIdx.x; i < 4096; i += 256) sW[i] = Wsl[i];
    __syncthreads();
    int idx = blockIdx.x * 256 + threadIdx.x;
    if (idx < 512) {
        int hh = idx >> 6, s = idx & 63;
        float t = fminf(fmaxf(temp[hh], 0.5f), 5.0f);
        float a = bsl[s];
        #pragma unroll 8
        for (int d = 0; d < 64; d++)
            a += bx[hh * 64 + d] * sW[d * 64 + s];
        g_biasL[hh * 64 + s] = a / t;
    }
}

// ---------------- fused kernel ----------------
// 1024 blocks x 512 threads, 2 CTAs/SM. Block converts its own x panel fp32->fp16
// into g_Xh at start (read back via L2). A/B streamed in K-chunks of 64 (cp.async,
// double-buffered). GEMM grid 4x4, warp tile 32x32. wn=0,1: f epilogue; wn=2,3:
// logits -> direct exp (bounded logits, temp pre-folded) + split psum exchange.
// Agg: 16 warps, tile 16(s)x16(d). Partials written with .cs (evict-first).
static constexpr int ACSTR = 72, BCSTR = 136, FSTR = 72, WGSTR = 72;
static constexpr int A_BUF = 128 * ACSTR * 2;                // 18432
static constexpr int B_BUF = 64 * BCSTR * 2;                 // 17408
static constexpr int OFF_A   = 0;                            // 2 bufs: 36864
static constexpr int OFF_B   = OFF_A + 2 * A_BUF;            // 36864..71680
static constexpr int OFF_FS  = OFF_B + 2 * B_BUF;            // 71680
static constexpr int OFF_WGT = OFF_FS + 128 * FSTR * 2;      // 90112
static constexpr int OFF_PSM = OFF_WGT + 128 * WGSTR * 2;    // 108544: float[128][2]
static constexpr int OFF_BF  = OFF_PSM + 1024;               // 109568: float[512]
static constexpr int OFF_BL  = OFF_BF + 2048;                // 111616: float[512]
static constexpr int OFF_NRM = OFF_BL + 2048;                // 113664: float[64]
static constexpr int FUSED_SMEM = OFF_NRM + 256;             // 113920 B

__global__ void __launch_bounds__(512, 2) fused_kernel(const float* __restrict__ x,
                                                       const float* __restrict__ bfx) {
    extern __shared__ char smem[];
    __half* Fs   = (__half*)(smem + OFF_FS);
    __half* Wgt  = (__half*)(smem + OFF_WGT);
    float*  psm  = (float*)(smem + OFF_PSM);
    float*  bfS  = (float*)(smem + OFF_BF);
    float*  blS  = (float*)(smem + OFF_BL);
    float*  nrm  = (float*)(smem + OFF_NRM);
    const uint32_t a_u32 = smem_u32(smem + OFF_A);
    const uint32_t b_u32 = smem_u32(smem + OFF_B);

    const int tid = threadIdx.x, warpid = tid >> 5, lane = tid & 31;
    const int blk = blockIdx.x;
    const __half* xh = g_Xh + (size_t)blk * 128 * 256;

    // prefetch B chunk 0 of head 0 first (overlaps the conversion below)
    {
        #pragma unroll
        for (int i = 0; i < 2; i++) {
            int e = tid + i * 512;
            int r = e >> 4, seg = e & 15;           // B: 16 segs/row
            cp16(b_u32 + (r * BCSTR + seg * 8) * 2, g_Wcomb + r * 1024 + seg * 8);
        }
        cp_commit();
    }

    // convert this block's x panel fp32 -> fp16 into g_Xh (read back via L2)
    {
        const float* xs = x + (size_t)blk * 128 * 256;
        __half* xd = g_Xh + (size_t)blk * 128 * 256;
        for (int i = tid; i < 4096; i += 512) {         // 8 halves per item
            float4 v0 = ((const float4*)xs)[i * 2];
            float4 v1 = ((const float4*)xs)[i * 2 + 1];
            __half2 hh[4];
            hh[0] = __floats2half2_rn(v0.x, v0.y);
            hh[1] = __floats2half2_rn(v0.z, v0.w);
            hh[2] = __floats2half2_rn(v1.x, v1.y);
            hh[3] = __floats2half2_rn(v1.z, v1.w);
            *(uint4*)(xd + (size_t)i * 8) = *(uint4*)hh;
        }
    }
    __threadfence();   // make panel visible to cp.async reads below

    // stage biases
    for (int i = tid; i < 512; i += 512) {
        bfS[i] = bfx[i];
        blS[i] = g_biasL[i];
    }
    if (tid < 64) nrm[tid] = 0.f;
    __syncthreads();   // conversion done block-wide before A prefetch

    // prefetch A chunk 0 (reads converted panel, L2-resident)
    {
        #pragma unroll
        for (int i = 0; i < 2; i++) {
            int e = tid + i * 512;
            int r = e >> 3, seg = e & 7;            // A: 8 segs/row
            cp16(a_u32 + (r * ACSTR + seg * 8) * 2, xh + r * 256 + seg * 8);
        }
        cp_commit();
    }

    const int wm = warpid >> 2, wn = warpid & 3;               // 4x4 grid, tile 32x32
    const int sA = (warpid >> 2) * 16, dA = (warpid & 3) * 16; // agg tiles

    for (int h = 0; h < 8; h++) {
        const float* bfh = bfS + h * 64;
        const float* blh = blS + h * 64;
        float acc[2][4][4];
        #pragma unroll
        for (int mi = 0; mi < 2; mi++)
            #pragma unroll
            for (int ni = 0; ni < 4; ni++)
                #pragma unroll
                for (int q = 0; q < 4; q++) acc[mi][ni][q] = 0.f;

        for (int c = 0; c < 4; c++) {
            cp_wait0();
            __syncthreads();    // chunk c visible; chunk c-1 buffer free

            // prefetch next chunk (next = h*4+c+1) into buffer (c+1)&1
            int nxt = h * 4 + c + 1;
            if (nxt < 32) {
                int nh = nxt >> 2, nc = nxt & 3;
                uint32_t ab = a_u32 + ((c + 1) & 1) * A_BUF;
                uint32_t bb = b_u32 + ((c + 1) & 1) * B_BUF;
                #pragma unroll
                for (int i = 0; i < 2; i++) {
                    int e = tid + i * 512;
                    int r = e >> 3, seg = e & 7;
                    cp16(ab + (r * ACSTR + seg * 8) * 2,
                         xh + r * 256 + nc * 64 + seg * 8);
                }
                #pragma unroll
                for (int i = 0; i < 2; i++) {
                    int e = tid + i * 512;
                    int r = e >> 4, seg = e & 15;
                    cp16(bb + (r * BCSTR + seg * 8) * 2,
                         g_Wcomb + (nc * 64 + r) * 1024 + nh * 128 + seg * 8);
                }
                cp_commit();
            }

            // compute chunk c: 4 k-steps, warp tile 32x32
            const uint32_t ab = a_u32 + (c & 1) * A_BUF;
            const uint32_t bb = b_u32 + (c & 1) * B_BUF;
            #pragma unroll
            for (int kk = 0; kk < 64; kk += 16) {
                uint32_t a[2][4], bfr[2][4];
                #pragma unroll
                for (int mi = 0; mi < 2; mi++)
                    ldm_x4(a[mi], ab + ((wm * 32 + mi * 16 + (lane & 15)) * ACSTR
                                        + kk + (lane >> 4) * 8) * 2);
                #pragma unroll
                for (int p = 0; p < 2; p++)
                    ldm_x4_t(bfr[p], bb + ((kk + (lane & 15)) * BCSTR
                                           + wn * 32 + p * 16 + (lane >> 4) * 8) * 2);
                #pragma unroll
                for (int mi = 0; mi < 2; mi++)
                    #pragma unroll
                    for (int ni = 0; ni < 4; ni++)
                        mma_f16(acc[mi][ni], a[mi], bfr[ni >> 1][(ni & 1) * 2],
                                bfr[ni >> 1][(ni & 1) * 2 + 1]);
            }
        }

        // ---- epilogue phase A: f-store || exp + partial sums ----
        if (wn < 2) {
            #pragma unroll
            for (int mi = 0; mi < 2; mi++) {
                int r0 = wm * 32 + mi * 16 + (lane >> 2);
                #pragma unroll
                for (int ni = 0; ni < 4; ni++) {
                    int cc = wn * 32 + ni * 8 + (lane & 3) * 2;
                    float b0 = bfh[cc], b1 = bfh[cc + 1];
                    *(__half2*)(Fs + r0 * FSTR + cc) =
                        __floats2half2_rn(acc[mi][ni][0] + b0, acc[mi][ni][1] + b1);
                    *(__half2*)(Fs + (r0 + 8) * FSTR + cc) =
                        __floats2half2_rn(acc[mi][ni][2] + b0, acc[mi][ni][3] + b1);
                }
            }
        } else {
            // logits (pre-scaled by 1/temp): direct exp, no max subtraction
            const int half_id = wn - 2;
            #pragma unroll
            for (int mi = 0; mi < 2; mi++) {
                int r0 = wm * 32 + mi * 16 + (lane >> 2);
                float s0 = 0.f, s8 = 0.f;
                #pragma unroll
                for (int ni = 0; ni < 4; ni++) {
                    int cc = half_id * 32 + ni * 8 + (lane & 3) * 2;
                    float b0 = blh[cc], b1 = blh[cc + 1];
                    acc[mi][ni][0] = __expf(acc[mi][ni][0] + b0);
                    acc[mi][ni][1] = __expf(acc[mi][ni][1] + b1);
                    acc[mi][ni][2] = __expf(acc[mi][ni][2] + b0);
                    acc[mi][ni][3] = __expf(acc[mi][ni][3] + b1);
                    s0 += acc[mi][ni][0] + acc[mi][ni][1];
                    s8 += acc[mi][ni][2] + acc[mi][ni][3];
                }
                #pragma unroll
                for (int off = 1; off <= 2; off <<= 1) {
                    s0 += __shfl_xor_sync(0xffffffffu, s0, off);
                    s8 += __shfl_xor_sync(0xffffffffu, s8, off);
                }
                if ((lane & 3) == 0) {
                    psm[r0 * 2 + half_id]       = s0;
                    psm[(r0 + 8) * 2 + half_id] = s8;
                }
            }
        }
        __syncthreads();   // psum exchange; Fs ready

        // ---- epilogue phase B: normalize, write weights, norm partials ----
        if (wn >= 2) {
            const int half_id = wn - 2;
            float ncol[4][2];
            #pragma unroll
            for (int ni = 0; ni < 4; ni++) { ncol[ni][0] = 0.f; ncol[ni][1] = 0.f; }
            #pragma unroll
            for (int mi = 0; mi < 2; mi++) {
                int r0 = wm * 32 + mi * 16 + (lane >> 2);
                float i0 = 1.f / (psm[r0 * 2] + psm[r0 * 2 + 1]);
                float i8 = 1.f / (psm[(r0 + 8) * 2] + psm[(r0 + 8) * 2 + 1]);
                #pragma unroll
                for (int ni = 0; ni < 4; ni++) {
                    int cc = half_id * 32 + ni * 8 + (lane & 3) * 2;
                    float w0 = acc[mi][ni][0] * i0, w1 = acc[mi][ni][1] * i0;
                    float w2 = acc[mi][ni][2] * i8, w3 = acc[mi][ni][3] * i8;
                    *(__half2*)(Wgt + r0 * WGSTR + cc)       = __floats2half2_rn(w0, w1);
                    *(__half2*)(Wgt + (r0 + 8) * WGSTR + cc) = __floats2half2_rn(w2, w3);
                    ncol[ni][0] += w0 + w2;
                    ncol[ni][1] += w1 + w3;
                }
            }
            #pragma unroll
            for (int ni = 0; ni < 4; ni++) {
                #pragma unroll
                for (int off = 4; off <= 16; off <<= 1) {
                    ncol[ni][0] += __shfl_xor_sync(0xffffffffu, ncol[ni][0], off);
                    ncol[ni][1] += __shfl_xor_sync(0xffffffffu, ncol[ni][1], off);
                }
            }
            if (lane < 4) {
                #pragma unroll
                for (int ni = 0; ni < 4; ni++) {
                    int cc = half_id * 32 + ni * 8 + lane * 2;
                    atomicAdd(&nrm[cc], ncol[ni][0]);
                    atomicAdd(&nrm[cc + 1], ncol[ni][1]);
                }
            }
        }
        __syncthreads();   // Wgt/nrm ready

        // ---- aggregation: out[s,d] = sum_t w[t,s] * f[t,d]; tile 16(s)x16(d) ----
        float ag[2][4];
        #pragma unroll
        for (int ng = 0; ng < 2; ng++)
            #pragma unroll
            for (int q = 0; q < 4; q++) ag[ng][q] = 0.f;

        #pragma unroll
        for (int kk = 0; kk < 128; kk += 16) {
            uint32_t a[4], bb[4];
            int trow = kk + (lane & 7) + ((lane >> 4) << 3);
            int scol = sA + (((lane >> 3) & 1) << 3);
            ldm_x4_t(a, smem_u32(Wgt + trow * WGSTR + scol));
            ldm_x4_t(bb, smem_u32(Fs + (kk + (lane & 15)) * FSTR + dA + (lane >> 4) * 8));
            mma_f16(ag[0], a, bb[0], bb[1]);
            mma_f16(ag[1], a, bb[2], bb[3]);
        }
        // streaming (evict-first) partial writes — no reuse until reduce
        __half* pt = g_Part + ((size_t)(blk * 8 + h)) * 4096;
        #pragma unroll
        for (int ng = 0; ng < 2; ng++) {
            int s = sA + (lane >> 2);
            int d = dA + ng * 8 + (lane & 3) * 2;
            __half2 v0 = __floats2half2_rn(ag[ng][0], ag[ng][1]);
            __half2 v1 = __floats2half2_rn(ag[ng][2], ag[ng][3]);
            __stcs((__half2*)(pt + s * 64 + d), v0);
            __stcs((__half2*)(pt + (s + 8) * 64 + d), v1);
        }
        if (tid < 64) {
            __stcs(&g_PartN[(blk * 8 + h) * 64 + tid], nrm[tid]);
            nrm[tid] = 0.f;
        }
        __syncthreads();   // protect Wgt/Fs/nrm for next head
    }
}

// ---------------- reduce: vectorized (uint4) two-level, streaming loads ----------------
__global__ void __launch_bounds__(256) reduce_kernel(float* __restrict__ out) {
    const int bid = blockIdx.x;
    const int bh = bid >> 4, sc = bid & 15;
    const int b = bh >> 3, h = bh & 7;
    const int tid = threadIdx.x, lane = tid & 31, warpid = tid >> 5;
    __shared__ float partial[8][256];
    __shared__ float invn[4];

    const int part = warpid;          // 0..7
    const int w = lane;               // 0..31
    const int sl = w >> 3, d8 = w & 7;
    float acc[8];
    #pragma unroll
    for (int j = 0; j < 8; j++) acc[j] = 0.f;
    const size_t base_off = (size_t)(sc * 4 + sl) * 64 + d8 * 8;
    for (int i = part * 64; i < part * 64 + 64; i++) {
        const __half* p = g_Part + ((size_t)((b * 512 + i) * 8 + h)) * 4096 + base_off;
        uint4 v = __ldcs((const uint4*)p);
        const __half2* h2 = (const __half2*)&v;
        #pragma unroll
        for (int j = 0; j < 4; j++) {
            float2 f = __half22float2(h2[j]);
            acc[j * 2] += f.x;
            acc[j * 2 + 1] += f.y;
        }
    }
    *(float4*)&partial[part][w * 8]     = make_float4(acc[0], acc[1], acc[2], acc[3]);
    *(float4*)&partial[part][w * 8 + 4] = make_float4(acc[4], acc[5], acc[6], acc[7]);

    // norm sums: warp 0, float4 across the 4 s-values of this chunk
    if (warpid == 0) {
        float4 ns = make_float4(0.f, 0.f, 0.f, 0.f);
        for (int i = lane; i < 512; i += 32) {
            float4 v = __ldcs((const float4*)(g_PartN
                + ((size_t)((b * 512 + i) * 8 + h)) * 64 + sc * 4));
            ns.x += v.x; ns.y += v.y; ns.z += v.z; ns.w += v.w;
        }
        #pragma unroll
        for (int off = 16; off > 0; off >>= 1) {
            ns.x += __shfl_xor_sync(0xffffffffu, ns.x, off);
            ns.y += __shfl_xor_sync(0xffffffffu, ns.y, off);
            ns.z += __shfl_xor_sync(0xffffffffu, ns.z, off);
            ns.w += __shfl_xor_sync(0xffffffffu, ns.w, off);
        }
        if (lane == 0) {
            invn[0] = 1.f / (ns.x + 0.01f);
            invn[1] = 1.f / (ns.y + 0.01f);
            invn[2] = 1.f / (ns.z + 0.01f);
            invn[3] = 1.f / (ns.w + 0.01f);
        }
    }
    __syncthreads();

    float s = 0.f;
    #pragma unroll
    for (int p2 = 0; p2 < 8; p2++) s += partial[p2][tid];
    const int sl2 = tid >> 6;
    out[bh * 4096 + (sc * 4 + sl2) * 64 + (tid & 63)] = s * invn[sl2];
}

// ---------------- launch: fused is 4th launch so ncu skip-5 profiles it ----------------
extern "C" void kernel_launch(void* const* d_in, const int* in_sizes, int n_in,
                              void* d_out, int out_size) {
    const float* x    = (const float*)d_in[0];
    const float* Wx   = (const float*)d_in[1];
    const float* bx   = (const float*)d_in[2];
    const float* Wfx  = (const float*)d_in[3];
    const float* bfx  = (const float*)d_in[4];
    const float* Wsl  = (const float*)d_in[5];
    const float* bsl  = (const float*)d_in[6];
    const float* temp = (const float*)d_in[7];

    cudaFuncSetAttribute(fused_kernel, cudaFuncAttributeMaxDynamicSharedMemorySize, FUSED_SMEM);

    prep_w<<<512, 256>>>(Wx, Wfx, Wsl, temp, 0);
    prep_w<<<512, 256>>>(Wx, Wfx, Wsl, temp, 1);
    prep_b<<<2, 256>>>(bx, Wsl, bsl, temp);
    fused_kernel<<<NBLK, 512, FUSED_SMEM>>>(x, bfx);
    reduce_kernel<<<256, 256>>>((float*)d_out);
}

// round 17
// speedup vs baseline: 1.0389x; 1.0389x over previous
#include <cuda_runtime.h>
#include <cuda_fp16.h>
#include <cstdint>
#include <cstddef>

// Problem constants
static constexpr int NN = 65536;
static constexpr int MROWS = 2 * NN;     // 131072 token rows
static constexpr int NBLK = MROWS / 128; // 1024 blocks

// ---------------- device scratch ----------------
// Combined per-head weights: [k=256][h*128 + (0..63: W_fx_h | 64..127: (W_x_h@W_slice)*invt)]
__device__ __half g_Wcomb[256 * 1024];
__device__ float  g_biasL[8 * 64];        // (b_x_h @ W_slice + b_slice) * invt
__device__ __half g_Xh[(size_t)MROWS * 256];        // 64 MB fp16 copy of x
__device__ __half g_Part[(size_t)NBLK * 8 * 4096];  // 64 MB fp16 partials
__device__ float  g_PartN[NBLK * 8 * 64];

// ---------------- ptx helpers ----------------
__device__ __forceinline__ uint32_t smem_u32(const void* p) {
    return (uint32_t)__cvta_generic_to_shared(p);
}
__device__ __forceinline__ void ldm_x4(uint32_t* r, uint32_t addr) {
    asm volatile("ldmatrix.sync.aligned.m8n8.x4.shared.b16 {%0,%1,%2,%3}, [%4];"
                 : "=r"(r[0]), "=r"(r[1]), "=r"(r[2]), "=r"(r[3]) : "r"(addr));
}
__device__ __forceinline__ void ldm_x4_t(uint32_t* r, uint32_t addr) {
    asm volatile("ldmatrix.sync.aligned.m8n8.x4.trans.shared.b16 {%0,%1,%2,%3}, [%4];"
                 : "=r"(r[0]), "=r"(r[1]), "=r"(r[2]), "=r"(r[3]) : "r"(addr));
}
__device__ __forceinline__ void mma_f16(float* c, const uint32_t* a, uint32_t b0, uint32_t b1) {
    asm volatile("mma.sync.aligned.m16n8k16.row.col.f32.f16.f16.f32 "
                 "{%0,%1,%2,%3}, {%4,%5,%6,%7}, {%8,%9}, {%0,%1,%2,%3};"
                 : "+f"(c[0]), "+f"(c[1]), "+f"(c[2]), "+f"(c[3])
                 : "r"(a[0]), "r"(a[1]), "r"(a[2]), "r"(a[3]), "r"(b0), "r"(b1));
}
__device__ __forceinline__ void cp16(uint32_t smem_addr, const void* gptr) {
    asm volatile("cp.async.cg.shared.global [%0], [%1], 16;"
                 :: "r"(smem_addr), "l"(gptr) : "memory");
}
__device__ __forceinline__ void cp_commit() {
    asm volatile("cp.async.commit_group;" ::: "memory");
}
__device__ __forceinline__ void cp_wait0() {
    asm volatile("cp.async.wait_group 0;" ::: "memory");
}

// ---------------- K1: weight prep (fold W_slice + 1/temp into logit weights) ----------------
__global__ void __launch_bounds__(256) prep_kernel(
        const float* __restrict__ Wx,  const float* __restrict__ bx,
        const float* __restrict__ Wfx,
        const float* __restrict__ Wsl, const float* __restrict__ bsl,
        const float* __restrict__ temp) {
    __shared__ float sW[64 * 64];
    for (int i = threadIdx.x; i < 4096; i += 256) sW[i] = Wsl[i];
    __syncthreads();

    int idx = blockIdx.x * blockDim.x + threadIdx.x;   // 0..262143
    int k = idx >> 10, j = idx & 1023;
    int h = j >> 7, c = j & 127;
    if (c < 64) {
        g_Wcomb[k * 1024 + h * 128 + c] = __float2half(Wfx[k * 512 + h * 64 + c]);
    } else {
        int s = c - 64;
        float t = fminf(fmaxf(temp[h], 0.5f), 5.0f);
        float invt = 1.0f / t;
        float acc = 0.f;
        #pragma unroll 8
        for (int d = 0; d < 64; d++)
            acc += Wx[k * 512 + h * 64 + d] * sW[d * 64 + s];
        g_Wcomb[k * 1024 + h * 128 + c] = __float2half(acc * invt);
    }
    if (idx < 512) {
        int hh = idx >> 6, s = idx & 63;
        float t = fminf(fmaxf(temp[hh], 0.5f), 5.0f);
        float a = bsl[s];
        #pragma unroll 8
        for (int d = 0; d < 64; d++)
            a += bx[hh * 64 + d] * sW[d * 64 + s];
        g_biasL[hh * 64 + s] = a / t;
    }
}

// ---------------- fused kernel ----------------
// 1024 blocks x 512 threads, 2 CTAs/SM. Block converts its own x panel fp32->fp16
// into g_Xh at start (read back via L2). A/B streamed in K-chunks of 64 (cp.async,
// double-buffered). GEMM grid 4x4, warp tile 32x32. wn=0,1: f epilogue; wn=2,3:
// logits -> direct exp (bounded logits, temp pre-folded) + split psum exchange.
// Agg: 16 warps, tile 16(s)x16(d). Partials written with .cs (evict-first).
static constexpr int ACSTR = 72, BCSTR = 136, FSTR = 72, WGSTR = 72;
static constexpr int A_BUF = 128 * ACSTR * 2;                // 18432
static constexpr int B_BUF = 64 * BCSTR * 2;                 // 17408
static constexpr int OFF_A   = 0;                            // 2 bufs: 36864
static constexpr int OFF_B   = OFF_A + 2 * A_BUF;            // 36864..71680
static constexpr int OFF_FS  = OFF_B + 2 * B_BUF;            // 71680
static constexpr int OFF_WGT = OFF_FS + 128 * FSTR * 2;      // 90112
static constexpr int OFF_PSM = OFF_WGT + 128 * WGSTR * 2;    // 108544: float[128][2]
static constexpr int OFF_BF  = OFF_PSM + 1024;               // 109568: float[512]
static constexpr int OFF_BL  = OFF_BF + 2048;                // 111616: float[512]
static constexpr int OFF_NRM = OFF_BL + 2048;                // 113664: float[64]
static constexpr int FUSED_SMEM = OFF_NRM + 256;             // 113920 B

__global__ void __launch_bounds__(512, 2) fused_kernel(const float* __restrict__ x,
                                                       const float* __restrict__ bfx) {
    extern __shared__ char smem[];
    __half* Fs   = (__half*)(smem + OFF_FS);
    __half* Wgt  = (__half*)(smem + OFF_WGT);
    float*  psm  = (float*)(smem + OFF_PSM);
    float*  bfS  = (float*)(smem + OFF_BF);
    float*  blS  = (float*)(smem + OFF_BL);
    float*  nrm  = (float*)(smem + OFF_NRM);
    const uint32_t a_u32 = smem_u32(smem + OFF_A);
    const uint32_t b_u32 = smem_u32(smem + OFF_B);

    const int tid = threadIdx.x, warpid = tid >> 5, lane = tid & 31;
    const int blk = blockIdx.x;
    const __half* xh = g_Xh + (size_t)blk * 128 * 256;

    // prefetch B chunk 0 of head 0 first (overlaps the conversion below)
    {
        #pragma unroll
        for (int i = 0; i < 2; i++) {
            int e = tid + i * 512;
            int r = e >> 4, seg = e & 15;           // B: 16 segs/row
            cp16(b_u32 + (r * BCSTR + seg * 8) * 2, g_Wcomb + r * 1024 + seg * 8);
        }
        cp_commit();
    }

    // convert this block's x panel fp32 -> fp16 into g_Xh (read back via L2);
    // x is read exactly once -> streaming loads keep reused data resident in L2
    {
        const float* xs = x + (size_t)blk * 128 * 256;
        __half* xd = g_Xh + (size_t)blk * 128 * 256;
        for (int i = tid; i < 4096; i += 512) {         // 8 halves per item
            float4 v0 = __ldcs((const float4*)xs + i * 2);
            float4 v1 = __ldcs((const float4*)xs + i * 2 + 1);
            __half2 hh[4];
            hh[0] = __floats2half2_rn(v0.x, v0.y);
            hh[1] = __floats2half2_rn(v0.z, v0.w);
            hh[2] = __floats2half2_rn(v1.x, v1.y);
            hh[3] = __floats2half2_rn(v1.z, v1.w);
            *(uint4*)(xd + (size_t)i * 8) = *(uint4*)hh;
        }
    }
    __threadfence();   // make panel visible to cp.async reads below

    // stage biases
    for (int i = tid; i < 512; i += 512) {
        bfS[i] = bfx[i];
        blS[i] = g_biasL[i];
    }
    if (tid < 64) nrm[tid] = 0.f;
    __syncthreads();   // conversion done block-wide before A prefetch

    // prefetch A chunk 0 (reads converted panel, L2-resident)
    {
        #pragma unroll
        for (int i = 0; i < 2; i++) {
            int e = tid + i * 512;
            int r = e >> 3, seg = e & 7;            // A: 8 segs/row
            cp16(a_u32 + (r * ACSTR + seg * 8) * 2, xh + r * 256 + seg * 8);
        }
        cp_commit();
    }

    const int wm = warpid >> 2, wn = warpid & 3;               // 4x4 grid, tile 32x32
    const int sA = (warpid >> 2) * 16, dA = (warpid & 3) * 16; // agg tiles

    for (int h = 0; h < 8; h++) {
        const float* bfh = bfS + h * 64;
        const float* blh = blS + h * 64;
        float acc[2][4][4];
        #pragma unroll
        for (int mi = 0; mi < 2; mi++)
            #pragma unroll
            for (int ni = 0; ni < 4; ni++)
                #pragma unroll
                for (int q = 0; q < 4; q++) acc[mi][ni][q] = 0.f;

        for (int c = 0; c < 4; c++) {
            cp_wait0();
            __syncthreads();    // chunk c visible; chunk c-1 buffer free

            // prefetch next chunk (next = h*4+c+1) into buffer (c+1)&1
            int nxt = h * 4 + c + 1;
            if (nxt < 32) {
                int nh = nxt >> 2, nc = nxt & 3;
                uint32_t ab = a_u32 + ((c + 1) & 1) * A_BUF;
                uint32_t bb = b_u32 + ((c + 1) & 1) * B_BUF;
                #pragma unroll
                for (int i = 0; i < 2; i++) {
                    int e = tid + i * 512;
                    int r = e >> 3, seg = e & 7;
                    cp16(ab + (r * ACSTR + seg * 8) * 2,
                         xh + r * 256 + nc * 64 + seg * 8);
                }
                #pragma unroll
                for (int i = 0; i < 2; i++) {
                    int e = tid + i * 512;
                    int r = e >> 4, seg = e & 15;
                    cp16(bb + (r * BCSTR + seg * 8) * 2,
                         g_Wcomb + (nc * 64 + r) * 1024 + nh * 128 + seg * 8);
                }
                cp_commit();
            }

            // compute chunk c: 4 k-steps, warp tile 32x32
            const uint32_t ab = a_u32 + (c & 1) * A_BUF;
            const uint32_t bb = b_u32 + (c & 1) * B_BUF;
            #pragma unroll
            for (int kk = 0; kk < 64; kk += 16) {
                uint32_t a[2][4], bfr[2][4];
                #pragma unroll
                for (int mi = 0; mi < 2; mi++)
                    ldm_x4(a[mi], ab + ((wm * 32 + mi * 16 + (lane & 15)) * ACSTR
                                        + kk + (lane >> 4) * 8) * 2);
                #pragma unroll
                for (int p = 0; p < 2; p++)
                    ldm_x4_t(bfr[p], bb + ((kk + (lane & 15)) * BCSTR
                                           + wn * 32 + p * 16 + (lane >> 4) * 8) * 2);
                #pragma unroll
                for (int mi = 0; mi < 2; mi++)
                    #pragma unroll
                    for (int ni = 0; ni < 4; ni++)
                        mma_f16(acc[mi][ni], a[mi], bfr[ni >> 1][(ni & 1) * 2],
                                bfr[ni >> 1][(ni & 1) * 2 + 1]);
            }
        }

        // ---- epilogue phase A: f-store || exp + partial sums ----
        if (wn < 2) {
            #pragma unroll
            for (int mi = 0; mi < 2; mi++) {
                int r0 = wm * 32 + mi * 16 + (lane >> 2);
                #pragma unroll
                for (int ni = 0; ni < 4; ni++) {
                    int cc = wn * 32 + ni * 8 + (lane & 3) * 2;
                    float b0 = bfh[cc], b1 = bfh[cc + 1];
                    *(__half2*)(Fs + r0 * FSTR + cc) =
                        __floats2half2_rn(acc[mi][ni][0] + b0, acc[mi][ni][1] + b1);
                    *(__half2*)(Fs + (r0 + 8) * FSTR + cc) =
                        __floats2half2_rn(acc[mi][ni][2] + b0, acc[mi][ni][3] + b1);
                }
            }
        } else {
            // logits (pre-scaled by 1/temp): direct exp, no max subtraction
            const int half_id = wn - 2;
            #pragma unroll
            for (int mi = 0; mi < 2; mi++) {
                int r0 = wm * 32 + mi * 16 + (lane >> 2);
                float s0 = 0.f, s8 = 0.f;
                #pragma unroll
                for (int ni = 0; ni < 4; ni++) {
                    int cc = half_id * 32 + ni * 8 + (lane & 3) * 2;
                    float b0 = blh[cc], b1 = blh[cc + 1];
                    acc[mi][ni][0] = __expf(acc[mi][ni][0] + b0);
                    acc[mi][ni][1] = __expf(acc[mi][ni][1] + b1);
                    acc[mi][ni][2] = __expf(acc[mi][ni][2] + b0);
                    acc[mi][ni][3] = __expf(acc[mi][ni][3] + b1);
                    s0 += acc[mi][ni][0] + acc[mi][ni][1];
                    s8 += acc[mi][ni][2] + acc[mi][ni][3];
                }
                #pragma unroll
                for (int off = 1; off <= 2; off <<= 1) {
                    s0 += __shfl_xor_sync(0xffffffffu, s0, off);
                    s8 += __shfl_xor_sync(0xffffffffu, s8, off);
                }
                if ((lane & 3) == 0) {
                    psm[r0 * 2 + half_id]       = s0;
                    psm[(r0 + 8) * 2 + half_id] = s8;
                }
            }
        }
        __syncthreads();   // psum exchange; Fs ready

        // ---- epilogue phase B: normalize, write weights, norm partials ----
        if (wn >= 2) {
            const int half_id = wn - 2;
            float ncol[4][2];
            #pragma unroll
            for (int ni = 0; ni < 4; ni++) { ncol[ni][0] = 0.f; ncol[ni][1] = 0.f; }
            #pragma unroll
            for (int mi = 0; mi < 2; mi++) {
                int r0 = wm * 32 + mi * 16 + (lane >> 2);
                float i0 = 1.f / (psm[r0 * 2] + psm[r0 * 2 + 1]);
                float i8 = 1.f / (psm[(r0 + 8) * 2] + psm[(r0 + 8) * 2 + 1]);
                #pragma unroll
                for (int ni = 0; ni < 4; ni++) {
                    int cc = half_id * 32 + ni * 8 + (lane & 3) * 2;
                    float w0 = acc[mi][ni][0] * i0, w1 = acc[mi][ni][1] * i0;
                    float w2 = acc[mi][ni][2] * i8, w3 = acc[mi][ni][3] * i8;
                    *(__half2*)(Wgt + r0 * WGSTR + cc)       = __floats2half2_rn(w0, w1);
                    *(__half2*)(Wgt + (r0 + 8) * WGSTR + cc) = __floats2half2_rn(w2, w3);
                    ncol[ni][0] += w0 + w2;
                    ncol[ni][1] += w1 + w3;
                }
            }
            #pragma unroll
            for (int ni = 0; ni < 4; ni++) {
                #pragma unroll
                for (int off = 4; off <= 16; off <<= 1) {
                    ncol[ni][0] += __shfl_xor_sync(0xffffffffu, ncol[ni][0], off);
                    ncol[ni][1] += __shfl_xor_sync(0xffffffffu, ncol[ni][1], off);
                }
            }
            if (lane < 4) {
                #pragma unroll
                for (int ni = 0; ni < 4; ni++) {
                    int cc = half_id * 32 + ni * 8 + lane * 2;
                    atomicAdd(&nrm[cc], ncol[ni][0]);
                    atomicAdd(&nrm[cc + 1], ncol[ni][1]);
                }
            }
        }
        __syncthreads();   // Wgt/nrm ready

        // ---- aggregation: out[s,d] = sum_t w[t,s] * f[t,d]; tile 16(s)x16(d) ----
        float ag[2][4];
        #pragma unroll
        for (int ng = 0; ng < 2; ng++)
            #pragma unroll
            for (int q = 0; q < 4; q++) ag[ng][q] = 0.f;

        #pragma unroll
        for (int kk = 0; kk < 128; kk += 16) {
            uint32_t a[4], bb[4];
            int trow = kk + (lane & 7) + ((lane >> 4) << 3);
            int scol = sA + (((lane >> 3) & 1) << 3);
            ldm_x4_t(a, smem_u32(Wgt + trow * WGSTR + scol));
            ldm_x4_t(bb, smem_u32(Fs + (kk + (lane & 15)) * FSTR + dA + (lane >> 4) * 8));
            mma_f16(ag[0], a, bb[0], bb[1]);
            mma_f16(ag[1], a, bb[2], bb[3]);
        }
        // streaming (evict-first) partial writes — no reuse until reduce
        __half* pt = g_Part + ((size_t)(blk * 8 + h)) * 4096;
        #pragma unroll
        for (int ng = 0; ng < 2; ng++) {
            int s = sA + (lane >> 2);
            int d = dA + ng * 8 + (lane & 3) * 2;
            __half2 v0 = __floats2half2_rn(ag[ng][0], ag[ng][1]);
            __half2 v1 = __floats2half2_rn(ag[ng][2], ag[ng][3]);
            __stcs((__half2*)(pt + s * 64 + d), v0);
            __stcs((__half2*)(pt + (s + 8) * 64 + d), v1);
        }
        if (tid < 64) {
            __stcs(&g_PartN[(blk * 8 + h) * 64 + tid], nrm[tid]);
            nrm[tid] = 0.f;
        }
        __syncthreads();   // protect Wgt/Fs/nrm for next head
    }
}

// ---------------- reduce: vectorized (uint4) two-level, streaming loads ----------------
__global__ void __launch_bounds__(256) reduce_kernel(float* __restrict__ out) {
    const int bid = blockIdx.x;
    const int bh = bid >> 4, sc = bid & 15;
    const int b = bh >> 3, h = bh & 7;
    const int tid = threadIdx.x, lane = tid & 31, warpid = tid >> 5;
    __shared__ float partial[8][256];
    __shared__ float invn[4];

    const int part = warpid;          // 0..7
    const int w = lane;               // 0..31
    const int sl = w >> 3, d8 = w & 7;
    float acc[8];
    #pragma unroll
    for (int j = 0; j < 8; j++) acc[j] = 0.f;
    const size_t base_off = (size_t)(sc * 4 + sl) * 64 + d8 * 8;
    for (int i = part * 64; i < part * 64 + 64; i++) {
        const __half* p = g_Part + ((size_t)((b * 512 + i) * 8 + h)) * 4096 + base_off;
        uint4 v = __ldcs((const uint4*)p);
        const __half2* h2 = (const __half2*)&v;
        #pragma unroll
        for (int j = 0; j < 4; j++) {
            float2 f = __half22float2(h2[j]);
            acc[j * 2] += f.x;
            acc[j * 2 + 1] += f.y;
        }
    }
    *(float4*)&partial[part][w * 8]     = make_float4(acc[0], acc[1], acc[2], acc[3]);
    *(float4*)&partial[part][w * 8 + 4] = make_float4(acc[4], acc[5], acc[6], acc[7]);

    // norm sums: warp 0, float4 across the 4 s-values of this chunk
    if (warpid == 0) {
        float4 ns = make_float4(0.f, 0.f, 0.f, 0.f);
        for (int i = lane; i < 512; i += 32) {
            float4 v = __ldcs((const float4*)(g_PartN
                + ((size_t)((b * 512 + i) * 8 + h)) * 64 + sc * 4));
            ns.x += v.x; ns.y += v.y; ns.z += v.z; ns.w += v.w;
        }
        #pragma unroll
        for (int off = 16; off > 0; off >>= 1) {
            ns.x += __shfl_xor_sync(0xffffffffu, ns.x, off);
            ns.y += __shfl_xor_sync(0xffffffffu, ns.y, off);
            ns.z += __shfl_xor_sync(0xffffffffu, ns.z, off);
            ns.w += __shfl_xor_sync(0xffffffffu, ns.w, off);
        }
        if (lane == 0) {
            invn[0] = 1.f / (ns.x + 0.01f);
            invn[1] = 1.f / (ns.y + 0.01f);
            invn[2] = 1.f / (ns.z + 0.01f);
            invn[3] = 1.f / (ns.w + 0.01f);
        }
    }
    __syncthreads();

    float s = 0.f;
    #pragma unroll
    for (int p2 = 0; p2 < 8; p2++) s += partial[p2][tid];
    const int sl2 = tid >> 6;
    out[bh * 4096 + (sc * 4 + sl2) * 64 + (tid & 63)] = s * invn[sl2];
}

// ---------------- launch: 3 launches only ----------------
extern "C" void kernel_launch(void* const* d_in, const int* in_sizes, int n_in,
                              void* d_out, int out_size) {
    const float* x    = (const float*)d_in[0];
    const float* Wx   = (const float*)d_in[1];
    const float* bx   = (const float*)d_in[2];
    const float* Wfx  = (const float*)d_in[3];
    const float* bfx  = (const float*)d_in[4];
    const float* Wsl  = (const float*)d_in[5];
    const float* bsl  = (const float*)d_in[6];
    const float* temp = (const float*)d_in[7];

    cudaFuncSetAttribute(fused_kernel, cudaFuncAttributeMaxDynamicSharedMemorySize, FUSED_SMEM);

    prep_kernel<<<1024, 256>>>(Wx, bx, Wfx, Wsl, bsl, temp);
    fused_kernel<<<NBLK, 512, FUSED_SMEM>>>(x, bfx);
    reduce_kernel<<<256, 256>>>((float*)d_out);
}